// round 1
// baseline (speedup 1.0000x reference)
#include <cuda_runtime.h>
#include <math.h>

#define HW 4096
#define CC 768
#define NHEADS 12
#define HD 64

// ---------------- scratch (device globals; no allocations allowed) ----------
__device__ float g_Q[(size_t)NHEADS * HW * HD];
__device__ float g_K[(size_t)NHEADS * HW * HD];
__device__ float g_V[(size_t)NHEADS * HW * HD];
__device__ float g_relh[(size_t)NHEADS * HW * HD];  // [head][token(h,w)][kh]
__device__ float g_relw[(size_t)NHEADS * HW * HD];  // [head][token(h,w)][kw]
__device__ float g_att[(size_t)HW * CC];            // attention out, token-major

// ---------------- projection GEMM: Y = X @ W^T + b ---------------------------
// X: [4096, 768] row-major; W: [768(out), 768(in)] row-major.
// DEST: 0->g_Q, 1->g_K, 2->g_V (head-major [head][token][hd]); 3-> Yout token-major.
// grid (12, 64), block 256 (16x16 threads, each 4x4 interleaved micro-tile).
template <int DEST>
__global__ void __launch_bounds__(256) proj_kernel(
    const float* __restrict__ Xin, const float* __restrict__ W,
    const float* __restrict__ bias, float* __restrict__ Yout)
{
    __shared__ float Xs[16][64];
    __shared__ float Ws[16][64];
    const float* X = (DEST == 3) ? (const float*)g_att : Xin;

    int tid = threadIdx.x;
    int tx = tid & 15, ty = tid >> 4;
    int lr = tid >> 2, lc = (tid & 3) * 4;   // loader: row 0..63, col4 0/4/8/12
    int m0 = blockIdx.y * 64, n0 = blockIdx.x * 64;

    float acc[4][4] = {};
    const float* xp = X + (size_t)(m0 + lr) * CC + lc;
    const float* wp = W + (size_t)(n0 + lr) * CC + lc;

    for (int k0 = 0; k0 < CC; k0 += 16) {
        float4 xv = *(const float4*)(xp + k0);
        float4 wv = *(const float4*)(wp + k0);
        __syncthreads();
        Xs[lc + 0][lr] = xv.x; Xs[lc + 1][lr] = xv.y;
        Xs[lc + 2][lr] = xv.z; Xs[lc + 3][lr] = xv.w;
        Ws[lc + 0][lr] = wv.x; Ws[lc + 1][lr] = wv.y;
        Ws[lc + 2][lr] = wv.z; Ws[lc + 3][lr] = wv.w;
        __syncthreads();
        #pragma unroll
        for (int k = 0; k < 16; k++) {
            float a[4], b[4];
            #pragma unroll
            for (int i = 0; i < 4; i++) a[i] = Xs[k][ty + i * 16];
            #pragma unroll
            for (int j = 0; j < 4; j++) b[j] = Ws[k][tx + j * 16];
            #pragma unroll
            for (int i = 0; i < 4; i++)
                #pragma unroll
                for (int j = 0; j < 4; j++)
                    acc[i][j] = fmaf(a[i], b[j], acc[i][j]);
        }
    }

    #pragma unroll
    for (int j = 0; j < 4; j++) {
        int n = n0 + tx + j * 16;
        float bv = bias[n];
        #pragma unroll
        for (int i = 0; i < 4; i++) {
            int mm = m0 + ty + i * 16;
            float v = acc[i][j] + bv;
            if (DEST == 0)
                g_Q[((size_t)(n >> 6) * HW + mm) * HD + (n & 63)] = v;
            else if (DEST == 1)
                g_K[((size_t)(n >> 6) * HW + mm) * HD + (n & 63)] = v;
            else if (DEST == 2)
                g_V[((size_t)(n >> 6) * HW + mm) * HD + (n & 63)] = v;
            else
                Yout[(size_t)mm * CC + n] = v;
        }
    }
}

// ---------------- decomposed rel-pos bias ------------------------------------
// axis 0 (rel_h): block = (h, head): out[head][h*64+w][k] = sum_c q * rph[h-k+63][c]
// axis 1 (rel_w): block = (w, head): out[head][h*64+w][k] = sum_c q * rpw[w-k+63][c]
// grid (64, 12, 2), block 256.
__global__ void __launch_bounds__(256) relpos_kernel(
    const float* __restrict__ rph, const float* __restrict__ rpw)
{
    __shared__ float Qs[64][65];
    __shared__ float Rs[64][65];
    int axis = blockIdx.z;
    int head = blockIdx.y;
    int a0 = blockIdx.x;
    int tid = threadIdx.x, tx = tid & 15, ty = tid >> 4;
    int lr = tid >> 2, lc = (tid & 3) * 4;

    int tok_l = (axis == 0) ? (a0 * 64 + lr) : (lr * 64 + a0);
    const float* rp = (axis == 0) ? rph : rpw;
    #pragma unroll
    for (int c0 = 0; c0 < 64; c0 += 16) {
        int c = lc + c0;
        float4 qv = *(const float4*)&g_Q[((size_t)head * HW + tok_l) * HD + c];
        Qs[lr][c + 0] = qv.x; Qs[lr][c + 1] = qv.y;
        Qs[lr][c + 2] = qv.z; Qs[lr][c + 3] = qv.w;
        float4 rv = *(const float4*)&rp[(size_t)(a0 - lr + 63) * HD + c];
        Rs[lr][c + 0] = rv.x; Rs[lr][c + 1] = rv.y;
        Rs[lr][c + 2] = rv.z; Rs[lr][c + 3] = rv.w;
    }
    __syncthreads();

    float acc[4][4] = {};
    #pragma unroll
    for (int d = 0; d < 64; d++) {
        float a[4], b[4];
        #pragma unroll
        for (int i = 0; i < 4; i++) a[i] = Qs[ty + i * 16][d];
        #pragma unroll
        for (int j = 0; j < 4; j++) b[j] = Rs[tx + j * 16][d];
        #pragma unroll
        for (int i = 0; i < 4; i++)
            #pragma unroll
            for (int j = 0; j < 4; j++)
                acc[i][j] = fmaf(a[i], b[j], acc[i][j]);
    }

    float* op = (axis == 0) ? g_relh : g_relw;
    #pragma unroll
    for (int i = 0; i < 4; i++) {
        int r = ty + i * 16;
        int tok = (axis == 0) ? (a0 * 64 + r) : (r * 64 + a0);
        #pragma unroll
        for (int j = 0; j < 4; j++)
            op[((size_t)head * HW + tok) * HD + tx + j * 16] = acc[i][j];
    }
}

// ---------------- flash attention with decomposed bias -----------------------
// grid (64 q-tiles, 12 heads), block 256. Dynamic smem: 5 * 64*65 floats.
// Key tile kt covers key tokens kt*64..kt*64+63 => kh = kt (const), kw = local.
__global__ void __launch_bounds__(256) attn_kernel()
{
    extern __shared__ float sm[];
    float* Qs = sm;                  // [64][65] (prescaled by 1/8)
    float* KP = sm + 64 * 65;        // K tile, then reused as P tile
    float* Vs = sm + 2 * 64 * 65;    // [64][65]
    float* Bh = sm + 3 * 64 * 65;    // [64 q][65] — column kt used per tile
    float* Bw = sm + 4 * 64 * 65;    // [64 q][65]

    int tid = threadIdx.x, tx = tid & 15, ty = tid >> 4;
    int lr = tid >> 2, lc = (tid & 3) * 4;
    int head = blockIdx.y;
    int q0 = blockIdx.x * 64;
    const float scale = 0.125f;  // 64^-0.5

    size_t qbase = ((size_t)head * HW + q0 + lr) * HD;
    #pragma unroll
    for (int c0 = 0; c0 < 64; c0 += 16) {
        int c = lc + c0;
        float4 qv = *(const float4*)&g_Q[qbase + c];
        Qs[lr * 65 + c + 0] = qv.x * scale; Qs[lr * 65 + c + 1] = qv.y * scale;
        Qs[lr * 65 + c + 2] = qv.z * scale; Qs[lr * 65 + c + 3] = qv.w * scale;
        float4 hv = *(const float4*)&g_relh[qbase + c];
        Bh[lr * 65 + c + 0] = hv.x; Bh[lr * 65 + c + 1] = hv.y;
        Bh[lr * 65 + c + 2] = hv.z; Bh[lr * 65 + c + 3] = hv.w;
        float4 wv = *(const float4*)&g_relw[qbase + c];
        Bw[lr * 65 + c + 0] = wv.x; Bw[lr * 65 + c + 1] = wv.y;
        Bw[lr * 65 + c + 2] = wv.z; Bw[lr * 65 + c + 3] = wv.w;
    }

    float mrow[4], lsum[4], O[4][4];
    #pragma unroll
    for (int i = 0; i < 4; i++) {
        mrow[i] = -INFINITY; lsum[i] = 0.f;
        #pragma unroll
        for (int j = 0; j < 4; j++) O[i][j] = 0.f;
    }

    for (int kt = 0; kt < HW / 64; kt++) {
        __syncthreads();  // prior PV readers of KP/Vs done
        size_t kvb = ((size_t)head * HW + kt * 64 + lr) * HD;
        #pragma unroll
        for (int c0 = 0; c0 < 64; c0 += 16) {
            int c = lc + c0;
            float4 kv = *(const float4*)&g_K[kvb + c];
            KP[lr * 65 + c + 0] = kv.x; KP[lr * 65 + c + 1] = kv.y;
            KP[lr * 65 + c + 2] = kv.z; KP[lr * 65 + c + 3] = kv.w;
            float4 vv = *(const float4*)&g_V[kvb + c];
            Vs[lr * 65 + c + 0] = vv.x; Vs[lr * 65 + c + 1] = vv.y;
            Vs[lr * 65 + c + 2] = vv.z; Vs[lr * 65 + c + 3] = vv.w;
        }
        __syncthreads();

        // S = (Q*scale) @ K^T + bias   (bias init: Bh[q][kt] + Bw[q][kw])
        float S[4][4];
        #pragma unroll
        for (int i = 0; i < 4; i++) {
            float bh = Bh[(ty + i * 16) * 65 + kt];
            #pragma unroll
            for (int j = 0; j < 4; j++)
                S[i][j] = bh + Bw[(ty + i * 16) * 65 + tx + j * 16];
        }
        #pragma unroll
        for (int d = 0; d < 64; d++) {
            float a[4], b[4];
            #pragma unroll
            for (int i = 0; i < 4; i++) a[i] = Qs[(ty + i * 16) * 65 + d];
            #pragma unroll
            for (int j = 0; j < 4; j++) b[j] = KP[(tx + j * 16) * 65 + d];
            #pragma unroll
            for (int i = 0; i < 4; i++)
                #pragma unroll
                for (int j = 0; j < 4; j++)
                    S[i][j] = fmaf(a[i], b[j], S[i][j]);
        }

        // row max across the 16 threads sharing a q-row (contiguous 16 lanes)
        float rmax[4];
        #pragma unroll
        for (int i = 0; i < 4; i++) {
            float v = fmaxf(fmaxf(S[i][0], S[i][1]), fmaxf(S[i][2], S[i][3]));
            #pragma unroll
            for (int off = 8; off >= 1; off >>= 1)
                v = fmaxf(v, __shfl_xor_sync(0xffffffffu, v, off));
            rmax[i] = v;
        }

        __syncthreads();  // all threads done reading KP as K

        #pragma unroll
        for (int i = 0; i < 4; i++) {
            float nm = fmaxf(mrow[i], rmax[i]);
            float al = __expf(mrow[i] - nm);
            mrow[i] = nm;
            float s = 0.f;
            #pragma unroll
            for (int j = 0; j < 4; j++) {
                S[i][j] = __expf(S[i][j] - nm);
                s += S[i][j];
                KP[(ty + i * 16) * 65 + tx + j * 16] = S[i][j];  // P tile
            }
            #pragma unroll
            for (int off = 8; off >= 1; off >>= 1)
                s += __shfl_xor_sync(0xffffffffu, s, off);
            lsum[i] = lsum[i] * al + s;
            #pragma unroll
            for (int j = 0; j < 4; j++) O[i][j] *= al;
        }
        __syncthreads();  // P visible

        // O += P @ V
        #pragma unroll
        for (int k = 0; k < 64; k++) {
            float a[4], b[4];
            #pragma unroll
            for (int i = 0; i < 4; i++) a[i] = KP[(ty + i * 16) * 65 + k];
            #pragma unroll
            for (int j = 0; j < 4; j++) b[j] = Vs[k * 65 + tx + j * 16];
            #pragma unroll
            for (int i = 0; i < 4; i++)
                #pragma unroll
                for (int j = 0; j < 4; j++)
                    O[i][j] = fmaf(a[i], b[j], O[i][j]);
        }
    }

    #pragma unroll
    for (int i = 0; i < 4; i++) {
        float inv = 1.0f / lsum[i];
        int tok = q0 + ty + i * 16;
        #pragma unroll
        for (int j = 0; j < 4; j++)
            g_att[(size_t)tok * CC + head * HD + tx + j * 16] = O[i][j] * inv;
    }
}

// ---------------- launch -----------------------------------------------------
extern "C" void kernel_launch(void* const* d_in, const int* in_sizes, int n_in,
                              void* d_out, int out_size)
{
    const float* hs  = (const float*)d_in[0];
    const float* w_q = (const float*)d_in[1];
    const float* b_q = (const float*)d_in[2];
    const float* w_k = (const float*)d_in[3];
    const float* b_k = (const float*)d_in[4];
    const float* w_v = (const float*)d_in[5];
    const float* b_v = (const float*)d_in[6];
    const float* w_o = (const float*)d_in[7];
    const float* b_o = (const float*)d_in[8];
    const float* rph = (const float*)d_in[9];
    const float* rpw = (const float*)d_in[10];
    float* out = (float*)d_out;

    dim3 gproj(CC / 64, HW / 64);  // (12, 64)
    proj_kernel<0><<<gproj, 256>>>(hs, w_q, b_q, nullptr);
    proj_kernel<1><<<gproj, 256>>>(hs, w_k, b_k, nullptr);
    proj_kernel<2><<<gproj, 256>>>(hs, w_v, b_v, nullptr);

    relpos_kernel<<<dim3(64, NHEADS, 2), 256>>>(rph, rpw);

    int smem = 5 * 64 * 65 * (int)sizeof(float);  // 83200 B
    cudaFuncSetAttribute(attn_kernel, cudaFuncAttributeMaxDynamicSharedMemorySize, smem);
    attn_kernel<<<dim3(HW / 64, NHEADS), 256, smem>>>();

    proj_kernel<3><<<gproj, 256>>>(nullptr, w_o, b_o, out);
}

// round 2
// speedup vs baseline: 3.1876x; 3.1876x over previous
#include <cuda_runtime.h>
#include <math.h>
#include <stdint.h>

#define HW 4096
#define CC 768
#define NHEADS 12
#define HD 64
#define SP 68   // smem row stride in floats (272B, 16B-aligned, bank-spreading)

// ---------------- scratch ----------------------------------------------------
__device__ float g_Q[(size_t)NHEADS * HW * HD];
__device__ float g_K[(size_t)NHEADS * HW * HD];
__device__ float g_V[(size_t)NHEADS * HW * HD];
__device__ float g_relh[(size_t)NHEADS * HD * HW];  // TRANSPOSED: [head][kh][tok]
__device__ float g_relw[(size_t)NHEADS * HW * HD];  // [head][tok][kw]
__device__ float g_att[(size_t)HW * CC];

// ---------------- helpers ----------------------------------------------------
__device__ __forceinline__ float f2tf(float x) {
    uint32_t u;
    asm("cvt.rna.tf32.f32 %0, %1;" : "=r"(u) : "f"(x));
    return __uint_as_float(u);
}

__device__ __forceinline__ void mma8(float* c,
                                     uint32_t a0, uint32_t a1, uint32_t a2, uint32_t a3,
                                     uint32_t b0, uint32_t b1) {
    asm volatile(
        "mma.sync.aligned.m16n8k8.row.col.f32.tf32.tf32.f32 "
        "{%0,%1,%2,%3}, {%4,%5,%6,%7}, {%8,%9}, {%0,%1,%2,%3};\n"
        : "+f"(c[0]), "+f"(c[1]), "+f"(c[2]), "+f"(c[3])
        : "r"(a0), "r"(a1), "r"(a2), "r"(a3), "r"(b0), "r"(b1));
}
#define FU(x) __float_as_uint(x)

// ---------------- projection GEMM (tf32 mma): Y = X @ W^T + b ----------------
// tile 128(m) x 64(n), K=768 in 12 chunks of 64. Block 256 thr = 8 warps,
// warp w: rows w*16..w*16+15, cols 0..63.
// DEST: 0..2 -> g_Q/g_K/g_V head-major; 3 -> Yout token-major (reads g_att).
template <int DEST>
__global__ void __launch_bounds__(256, 2) projmma_kernel(
    const float* __restrict__ Xin, const float* __restrict__ W,
    const float* __restrict__ bias, float* __restrict__ Yout)
{
    extern __shared__ float sm[];
    float* Xs = sm;              // [128][SP]
    float* Ws = sm + 128 * SP;   // [64][SP]
    const float* X = (DEST == 3) ? (const float*)g_att : Xin;

    int tid = threadIdx.x;
    int warp = tid >> 5, lane = tid & 31, g = lane >> 2, c4 = lane & 3;
    int m0 = blockIdx.y * 128, n0 = blockIdx.x * 64;
    int r0 = warp * 16 + g, r1 = r0 + 8;

    float acc[8][4] = {};

    for (int k0 = 0; k0 < CC; k0 += 64) {
        __syncthreads();
        #pragma unroll
        for (int i = 0; i < 8; i++) {                 // X: 128x64 = 2048 float4
            int idx = tid + i * 256;
            int row = idx >> 4, j = idx & 15;
            float4 v = *(const float4*)(X + (size_t)(m0 + row) * CC + k0 + 4 * j);
            float4 t = make_float4(f2tf(v.x), f2tf(v.y), f2tf(v.z), f2tf(v.w));
            *(float4*)(Xs + row * SP + 4 * j) = t;
        }
        #pragma unroll
        for (int i = 0; i < 4; i++) {                 // W: 64x64 = 1024 float4
            int idx = tid + i * 256;
            int row = idx >> 4, j = idx & 15;
            float4 v = *(const float4*)(W + (size_t)(n0 + row) * CC + k0 + 4 * j);
            float4 t = make_float4(f2tf(v.x), f2tf(v.y), f2tf(v.z), f2tf(v.w));
            *(float4*)(Ws + row * SP + 4 * j) = t;
        }
        __syncthreads();

        #pragma unroll
        for (int s = 0; s < 8; s++) {
            int kb = 8 * s;
            uint32_t a0 = FU(Xs[r0 * SP + kb + c4]);
            uint32_t a1 = FU(Xs[r1 * SP + kb + c4]);
            uint32_t a2 = FU(Xs[r0 * SP + kb + c4 + 4]);
            uint32_t a3 = FU(Xs[r1 * SP + kb + c4 + 4]);
            #pragma unroll
            for (int n = 0; n < 8; n++) {
                uint32_t b0 = FU(Ws[(8 * n + g) * SP + kb + c4]);
                uint32_t b1 = FU(Ws[(8 * n + g) * SP + kb + c4 + 4]);
                mma8(acc[n], a0, a1, a2, a3, b0, b1);
            }
        }
    }

    #pragma unroll
    for (int n = 0; n < 8; n++) {
        int hcol = 8 * n + 2 * c4;           // 0..63 within n-block
        int col = n0 + hcol;
        float b0v = bias[col], b1v = bias[col + 1];
        float2 v0 = make_float2(acc[n][0] + b0v, acc[n][1] + b1v);
        float2 v1 = make_float2(acc[n][2] + b0v, acc[n][3] + b1v);
        int mr0 = m0 + r0, mr1 = m0 + r1;
        if (DEST == 0) {
            *(float2*)(g_Q + ((size_t)(col >> 6) * HW + mr0) * HD + (col & 63)) = v0;
            *(float2*)(g_Q + ((size_t)(col >> 6) * HW + mr1) * HD + (col & 63)) = v1;
        } else if (DEST == 1) {
            *(float2*)(g_K + ((size_t)(col >> 6) * HW + mr0) * HD + (col & 63)) = v0;
            *(float2*)(g_K + ((size_t)(col >> 6) * HW + mr1) * HD + (col & 63)) = v1;
        } else if (DEST == 2) {
            *(float2*)(g_V + ((size_t)(col >> 6) * HW + mr0) * HD + (col & 63)) = v0;
            *(float2*)(g_V + ((size_t)(col >> 6) * HW + mr1) * HD + (col & 63)) = v1;
        } else {
            *(float2*)(Yout + (size_t)mr0 * CC + col) = v0;
            *(float2*)(Yout + (size_t)mr1 * CC + col) = v1;
        }
    }
}

// ---------------- decomposed rel-pos bias (FFMA, small) ----------------------
// axis 0 -> g_relh TRANSPOSED [head][kh][tok]; axis 1 -> g_relw [head][tok][kw]
__global__ void __launch_bounds__(256) relpos_kernel(
    const float* __restrict__ rph, const float* __restrict__ rpw)
{
    __shared__ float Qs[64][65];
    __shared__ float Rs[64][65];
    int axis = blockIdx.z, head = blockIdx.y, a0 = blockIdx.x;
    int tid = threadIdx.x, tx = tid & 15, ty = tid >> 4;
    int lr = tid >> 2, lc = (tid & 3) * 4;

    int tok_l = (axis == 0) ? (a0 * 64 + lr) : (lr * 64 + a0);
    const float* rp = (axis == 0) ? rph : rpw;
    #pragma unroll
    for (int c0 = 0; c0 < 64; c0 += 16) {
        int c = lc + c0;
        float4 qv = *(const float4*)&g_Q[((size_t)head * HW + tok_l) * HD + c];
        Qs[lr][c + 0] = qv.x; Qs[lr][c + 1] = qv.y;
        Qs[lr][c + 2] = qv.z; Qs[lr][c + 3] = qv.w;
        float4 rv = *(const float4*)&rp[(size_t)(a0 - lr + 63) * HD + c];
        Rs[lr][c + 0] = rv.x; Rs[lr][c + 1] = rv.y;
        Rs[lr][c + 2] = rv.z; Rs[lr][c + 3] = rv.w;
    }
    __syncthreads();

    float acc[4][4] = {};
    #pragma unroll
    for (int d = 0; d < 64; d++) {
        float a[4], b[4];
        #pragma unroll
        for (int i = 0; i < 4; i++) a[i] = Qs[ty + i * 16][d];
        #pragma unroll
        for (int j = 0; j < 4; j++) b[j] = Rs[tx + j * 16][d];
        #pragma unroll
        for (int i = 0; i < 4; i++)
            #pragma unroll
            for (int j = 0; j < 4; j++)
                acc[i][j] = fmaf(a[i], b[j], acc[i][j]);
    }

    #pragma unroll
    for (int i = 0; i < 4; i++) {
        int r = ty + i * 16;
        int tok = (axis == 0) ? (a0 * 64 + r) : (r * 64 + a0);
        #pragma unroll
        for (int j = 0; j < 4; j++) {
            int k = tx + j * 16;
            if (axis == 0)
                g_relh[((size_t)head * HD + k) * HW + tok] = acc[i][j];
            else
                g_relw[((size_t)head * HW + tok) * HD + k] = acc[i][j];
        }
    }
}

// ---------------- flash attention, tf32 mma ----------------------------------
// q-tile 128, key-tile 64 (= one image row => kh const per tile, kw = local).
// Block 256 thr = 8 warps; warp w owns q rows w*16..w*16+15 x all 64 key cols.
__global__ void __launch_bounds__(256, 1) attnmma_kernel()
{
    extern __shared__ float sm[];
    float* Qs  = sm;                  // [128][SP] tf32, prescaled by 0.125
    float* Ks  = Qs + 128 * SP;       // [64][SP]  tf32
    float* Vt  = Ks + 64 * SP;        // [64][SP]  tf32, TRANSPOSED: [d][key]
    float* Ps  = Vt + 64 * SP;        // [128][SP] tf32 P tile
    float* Bws = Ps + 128 * SP;       // [128][SP] f32 rel_w bias
    float* Bhs = Bws + 128 * SP;      // [128] f32 rel_h column for this key tile

    int tid = threadIdx.x;
    int warp = tid >> 5, lane = tid & 31, g = lane >> 2, c4 = lane & 3;
    int head = blockIdx.y, q0 = blockIdx.x * 128;
    int r0 = warp * 16 + g, r1 = r0 + 8;

    // prologue: Q (prescaled, tf32) + Bw bias
    size_t qb = (size_t)head * HW + q0;
    #pragma unroll
    for (int i = 0; i < 8; i++) {
        int idx = tid + i * 256;
        int row = idx >> 4, j = idx & 15;
        float4 v = *(const float4*)(g_Q + (qb + row) * HD + 4 * j);
        float4 t = make_float4(f2tf(v.x * 0.125f), f2tf(v.y * 0.125f),
                               f2tf(v.z * 0.125f), f2tf(v.w * 0.125f));
        *(float4*)(Qs + row * SP + 4 * j) = t;
        float4 w = *(const float4*)(g_relw + (qb + row) * HD + 4 * j);
        *(float4*)(Bws + row * SP + 4 * j) = w;
    }

    float O[8][4] = {};
    float m0r = -INFINITY, m1r = -INFINITY, l0 = 0.f, l1 = 0.f;

    for (int kt = 0; kt < HW / 64; kt++) {
        __syncthreads();  // protect Ks/Vt/Bhs/Ps from previous-iter readers
        size_t kb = (size_t)head * HW + kt * 64;
        #pragma unroll
        for (int i = 0; i < 4; i++) {                 // K: coalesced, direct
            int idx = tid + i * 256;
            int row = idx >> 4, j = idx & 15;
            float4 v = *(const float4*)(g_K + (kb + row) * HD + 4 * j);
            float4 t = make_float4(f2tf(v.x), f2tf(v.y), f2tf(v.z), f2tf(v.w));
            *(float4*)(Ks + row * SP + 4 * j) = t;
        }
        #pragma unroll
        for (int i = 0; i < 4; i++) {                 // V: transpose-scatter
            int idx = tid + i * 256;
            int key = idx & 63, j = idx >> 6;         // lanes vary key -> conflict-free STS
            float4 v = *(const float4*)(g_V + (kb + key) * HD + 4 * j);
            Vt[(4 * j + 0) * SP + key] = f2tf(v.x);
            Vt[(4 * j + 1) * SP + key] = f2tf(v.y);
            Vt[(4 * j + 2) * SP + key] = f2tf(v.z);
            Vt[(4 * j + 3) * SP + key] = f2tf(v.w);
        }
        if (tid < 128)
            Bhs[tid] = g_relh[((size_t)head * HD + kt) * HW + q0 + tid];
        __syncthreads();

        // ---- S = (Q/8) @ K^T + bias ----
        float S[8][4];
        float bh0 = Bhs[r0], bh1 = Bhs[r1];
        #pragma unroll
        for (int n = 0; n < 8; n++) {
            int col = 8 * n + 2 * c4;
            float2 w0 = *(const float2*)(Bws + r0 * SP + col);
            float2 w1 = *(const float2*)(Bws + r1 * SP + col);
            S[n][0] = bh0 + w0.x; S[n][1] = bh0 + w0.y;
            S[n][2] = bh1 + w1.x; S[n][3] = bh1 + w1.y;
        }
        #pragma unroll
        for (int s = 0; s < 8; s++) {
            int kb8 = 8 * s;
            uint32_t a0 = FU(Qs[r0 * SP + kb8 + c4]);
            uint32_t a1 = FU(Qs[r1 * SP + kb8 + c4]);
            uint32_t a2 = FU(Qs[r0 * SP + kb8 + c4 + 4]);
            uint32_t a3 = FU(Qs[r1 * SP + kb8 + c4 + 4]);
            #pragma unroll
            for (int n = 0; n < 8; n++) {
                uint32_t b0 = FU(Ks[(8 * n + g) * SP + kb8 + c4]);
                uint32_t b1 = FU(Ks[(8 * n + g) * SP + kb8 + c4 + 4]);
                mma8(S[n], a0, a1, a2, a3, b0, b1);
            }
        }

        // ---- online softmax (rows private to quad) ----
        float mx0 = -INFINITY, mx1 = -INFINITY;
        #pragma unroll
        for (int n = 0; n < 8; n++) {
            mx0 = fmaxf(mx0, fmaxf(S[n][0], S[n][1]));
            mx1 = fmaxf(mx1, fmaxf(S[n][2], S[n][3]));
        }
        mx0 = fmaxf(mx0, __shfl_xor_sync(0xffffffffu, mx0, 1));
        mx0 = fmaxf(mx0, __shfl_xor_sync(0xffffffffu, mx0, 2));
        mx1 = fmaxf(mx1, __shfl_xor_sync(0xffffffffu, mx1, 1));
        mx1 = fmaxf(mx1, __shfl_xor_sync(0xffffffffu, mx1, 2));
        float nm0 = fmaxf(m0r, mx0), nm1 = fmaxf(m1r, mx1);
        float al0 = __expf(m0r - nm0), al1 = __expf(m1r - nm1);
        m0r = nm0; m1r = nm1;
        float s0 = 0.f, s1 = 0.f;
        #pragma unroll
        for (int n = 0; n < 8; n++) {
            float p00 = __expf(S[n][0] - nm0), p01 = __expf(S[n][1] - nm0);
            float p10 = __expf(S[n][2] - nm1), p11 = __expf(S[n][3] - nm1);
            s0 += p00 + p01; s1 += p10 + p11;
            int col = 8 * n + 2 * c4;
            *(float2*)(Ps + r0 * SP + col) = make_float2(f2tf(p00), f2tf(p01));
            *(float2*)(Ps + r1 * SP + col) = make_float2(f2tf(p10), f2tf(p11));
            O[n][0] *= al0; O[n][1] *= al0; O[n][2] *= al1; O[n][3] *= al1;
        }
        s0 += __shfl_xor_sync(0xffffffffu, s0, 1);
        s0 += __shfl_xor_sync(0xffffffffu, s0, 2);
        s1 += __shfl_xor_sync(0xffffffffu, s1, 1);
        s1 += __shfl_xor_sync(0xffffffffu, s1, 2);
        l0 = l0 * al0 + s0;
        l1 = l1 * al1 + s1;
        __syncwarp();  // P rows are warp-private; make stores visible

        // ---- O += P @ V ----
        #pragma unroll
        for (int s = 0; s < 8; s++) {
            int kb8 = 8 * s;
            uint32_t a0 = FU(Ps[r0 * SP + kb8 + c4]);
            uint32_t a1 = FU(Ps[r1 * SP + kb8 + c4]);
            uint32_t a2 = FU(Ps[r0 * SP + kb8 + c4 + 4]);
            uint32_t a3 = FU(Ps[r1 * SP + kb8 + c4 + 4]);
            #pragma unroll
            for (int n = 0; n < 8; n++) {
                uint32_t b0 = FU(Vt[(8 * n + g) * SP + kb8 + c4]);
                uint32_t b1 = FU(Vt[(8 * n + g) * SP + kb8 + c4 + 4]);
                mma8(O[n], a0, a1, a2, a3, b0, b1);
            }
        }
    }

    float inv0 = 1.0f / l0, inv1 = 1.0f / l1;
    #pragma unroll
    for (int n = 0; n < 8; n++) {
        int d = 8 * n + 2 * c4;
        *(float2*)(g_att + (size_t)(q0 + r0) * CC + head * HD + d) =
            make_float2(O[n][0] * inv0, O[n][1] * inv0);
        *(float2*)(g_att + (size_t)(q0 + r1) * CC + head * HD + d) =
            make_float2(O[n][2] * inv1, O[n][3] * inv1);
    }
}

// ---------------- launch -----------------------------------------------------
extern "C" void kernel_launch(void* const* d_in, const int* in_sizes, int n_in,
                              void* d_out, int out_size)
{
    const float* hs  = (const float*)d_in[0];
    const float* w_q = (const float*)d_in[1];
    const float* b_q = (const float*)d_in[2];
    const float* w_k = (const float*)d_in[3];
    const float* b_k = (const float*)d_in[4];
    const float* w_v = (const float*)d_in[5];
    const float* b_v = (const float*)d_in[6];
    const float* w_o = (const float*)d_in[7];
    const float* b_o = (const float*)d_in[8];
    const float* rph = (const float*)d_in[9];
    const float* rpw = (const float*)d_in[10];
    float* out = (float*)d_out;

    int proj_smem = (128 * SP + 64 * SP) * (int)sizeof(float);   // 52224 B
    int att_smem  = (128 * SP * 3 + 64 * SP * 2 + 128) * (int)sizeof(float);  // 139,264+512

    cudaFuncSetAttribute(projmma_kernel<0>, cudaFuncAttributeMaxDynamicSharedMemorySize, proj_smem);
    cudaFuncSetAttribute(projmma_kernel<1>, cudaFuncAttributeMaxDynamicSharedMemorySize, proj_smem);
    cudaFuncSetAttribute(projmma_kernel<2>, cudaFuncAttributeMaxDynamicSharedMemorySize, proj_smem);
    cudaFuncSetAttribute(projmma_kernel<3>, cudaFuncAttributeMaxDynamicSharedMemorySize, proj_smem);
    cudaFuncSetAttribute(attnmma_kernel, cudaFuncAttributeMaxDynamicSharedMemorySize, att_smem);

    dim3 gproj(CC / 64, HW / 128);  // (12, 32)
    projmma_kernel<0><<<gproj, 256, proj_smem>>>(hs, w_q, b_q, nullptr);
    projmma_kernel<1><<<gproj, 256, proj_smem>>>(hs, w_k, b_k, nullptr);
    projmma_kernel<2><<<gproj, 256, proj_smem>>>(hs, w_v, b_v, nullptr);

    relpos_kernel<<<dim3(64, NHEADS, 2), 256>>>(rph, rpw);

    attnmma_kernel<<<dim3(HW / 128, NHEADS), 256, att_smem>>>();

    projmma_kernel<3><<<gproj, 256, proj_smem>>>(nullptr, w_o, b_o, out);
}